// round 15
// baseline (speedup 1.0000x reference)
#include <cuda_runtime.h>
#include <cuda_fp16.h>
#include <math.h>
#include <stdint.h>

#define NPTS   262144
#define HG     200
#define WGRID  176
#define HW     35200
#define CBEV   256
#define CDIR   176
#define CIN    432
#define COUT   128
#define NPIX   140800

// Projected BEV features, fp16: G[pixel][128] = im[pixel][:] @ W[:,176:432]^T
__device__ __half g_G[(size_t)NPIX * COUT];   // 36 MB (L2-resident)

// ---------------------------------------------------------------------------
__device__ __forceinline__ unsigned smem_u32(const void* p) {
    unsigned a;
    asm("{ .reg .u64 t; cvta.to.shared.u64 t, %1; cvt.u32.u64 %0, t; }"
        : "=r"(a) : "l"(p));
    return a;
}
#define CP_ASYNC16(dst, src) \
    asm volatile("cp.async.cg.shared.global [%0], [%1], 16;\n" :: "r"(dst), "l"(src))
#define CP_COMMIT() asm volatile("cp.async.commit_group;\n")
#define CP_WAIT(n)  asm volatile("cp.async.wait_group %0;\n" :: "n"(n))

// Raw fp32 bits into tf32 MMA (RZ truncation in HW)
__device__ __forceinline__ void mma_tf32(float* c, const unsigned* a, const unsigned* b) {
    asm volatile(
        "mma.sync.aligned.m16n8k8.row.col.f32.tf32.tf32.f32 "
        "{%0,%1,%2,%3},{%4,%5,%6,%7},{%8,%9},{%0,%1,%2,%3};"
        : "+f"(c[0]), "+f"(c[1]), "+f"(c[2]), "+f"(c[3])
        : "r"(a[0]), "r"(a[1]), "r"(a[2]), "r"(a[3]), "r"(b[0]), "r"(b[1]));
}

// ---------------------------------------------------------------------------
// Kernel A (round-14 verbatim): G = im @ W_bev^T, fp16 output.
// Tile 128x128, 512 threads, BK=32 (8 stages), 3-buffer pipeline.
// ---------------------------------------------------------------------------
#define ASTR_P 136
#define NSTG_P 8
#define PROJ_BS_OFF 52224
#define PROJ_SMEM   (52224 + 49152)

__global__ __launch_bounds__(512, 2)
void proj_kernel(const float* __restrict__ sp, const float* __restrict__ Wmat) {
    extern __shared__ char dsm[];
    float (*As)[32][ASTR_P] = (float (*)[32][ASTR_P])dsm;
    float (*Bs)[128][32]    = (float (*)[128][32])(dsm + PROJ_BS_OFF);

    const int t    = threadIdx.x;
    const int lane = t & 31;
    const int wid  = t >> 5;
    const int wm   = wid & 3;
    const int wn   = wid >> 2;
    const int qg   = lane >> 2;
    const int ql   = lane & 3;

    const int pixBase = blockIdx.x * 128;
    const int b       = pixBase / HW;
    const int pixInB  = pixBase - b * HW;
    const float* Abase = sp + (size_t)b * CBEV * HW + pixInB;

    const unsigned uA = smem_u32(&As[0][0][0]);
    const unsigned uB = smem_u32(&Bs[0][0][0]);

    float acc[2][4][4];
    #pragma unroll
    for (int i = 0; i < 2; i++)
        #pragma unroll
        for (int j = 0; j < 4; j++)
            #pragma unroll
            for (int v = 0; v < 4; v++) acc[i][j][v] = 0.0f;

    auto load_stage = [&](int s, int buf) {
        int k0 = s * 32;
        #pragma unroll
        for (int i = 0; i < 2; i++) {
            int lin = t + i * 512;
            int k   = lin >> 5;
            int m4  = (lin & 31) << 2;
            unsigned dst = uA + ((unsigned)(buf * 32 + k) * ASTR_P + m4) * 4u;
            CP_ASYNC16(dst, Abase + (size_t)(k0 + k) * HW + m4);
        }
        #pragma unroll
        for (int i = 0; i < 2; i++) {
            int lin = t + i * 512;
            int n   = lin >> 3;
            int k4  = lin & 7;
            unsigned wsw = (unsigned)((k4 * 4) ^ ((n & 7) << 2));
            unsigned dst = uB + ((unsigned)(buf * 128 + n) * 32 + wsw) * 4u;
            CP_ASYNC16(dst, Wmat + (size_t)n * CIN + CDIR + k0 + k4 * 4);
        }
        CP_COMMIT();
    };

    load_stage(0, 0);
    load_stage(1, 1);

    for (int s = 0; s < NSTG_P; s++) {
        int buf = s - (s / 3) * 3;
        if (s < NSTG_P - 1) CP_WAIT(1); else CP_WAIT(0);
        __syncthreads();
        if (s + 2 < NSTG_P) load_stage(s + 2, (s + 2) % 3);

        #pragma unroll
        for (int kk = 0; kk < 32; kk += 8) {
            int kc = kk + ql;
            unsigned a[2][4], bb[4][2];
            #pragma unroll
            for (int mt = 0; mt < 2; mt++) {
                int r = wm * 32 + mt * 16 + qg;
                a[mt][0] = __float_as_uint(As[buf][kc][r]);
                a[mt][1] = __float_as_uint(As[buf][kc][r + 8]);
                a[mt][2] = __float_as_uint(As[buf][kc + 4][r]);
                a[mt][3] = __float_as_uint(As[buf][kc + 4][r + 8]);
            }
            #pragma unroll
            for (int nt = 0; nt < 4; nt++) {
                int c   = wn * 32 + nt * 8 + qg;
                int sw0 = kc ^ ((c & 7) << 2);
                int sw1 = (kc + 4) ^ ((c & 7) << 2);
                bb[nt][0] = __float_as_uint(Bs[buf][c][sw0]);
                bb[nt][1] = __float_as_uint(Bs[buf][c][sw1]);
            }
            #pragma unroll
            for (int mt = 0; mt < 2; mt++)
                #pragma unroll
                for (int nt = 0; nt < 4; nt++)
                    mma_tf32(acc[mt][nt], a[mt], bb[nt]);
        }
    }

    #pragma unroll
    for (int mt = 0; mt < 2; mt++) {
        int r0 = pixBase + wm * 32 + mt * 16 + qg;
        #pragma unroll
        for (int nt = 0; nt < 4; nt++) {
            int n = wn * 32 + nt * 8 + 2 * ql;
            *(__half2*)&g_G[(size_t)r0 * COUT + n] =
                __floats2half2_rn(acc[mt][nt][0], acc[mt][nt][1]);
            *(__half2*)&g_G[(size_t)(r0 + 8) * COUT + n] =
                __floats2half2_rn(acc[mt][nt][2], acc[mt][nt][3]);
        }
    }
}

// ---------------------------------------------------------------------------
// Kernel B: 128pts x 128out, 512 threads, BK=32 (6 stages), 3-buffer
// pipeline. NEW: k-permuted LDS.64 fragment loads — smem word kk+2ql feeds
// MMA k-slot ql, word kk+2ql+1 feeds slot ql+4, identically for A and B
// (k-sum order free). Every fragment pair is one 8B load: frag instructions
// per k-step 16 -> 8. Both tiles use 32-word XOR rows, swizzle ((row&3)<<3)
// (disjoint bit ranges with 2ql -> conflict-free LDS.64 half-warps; 16B
// cp.async chunks stay 4-aligned under the 8-aligned XOR).
// Dynamic smem: As[3][128][32] @0 (49152B), Bs[3][128][32] @49152 (49152B).
// ---------------------------------------------------------------------------
#define BEVSTR 136
#define NSTG_Q 6
#define PT_BS_OFF 49152
#define PT_SMEM   98304

__global__ __launch_bounds__(512, 2)
void point_kernel(const float* __restrict__ pc,
                  const float* __restrict__ f16,
                  const float* __restrict__ f32,
                  const float* __restrict__ f64a,
                  const float* __restrict__ f64b,
                  const float* __restrict__ Wmat,
                  const float* __restrict__ gamma,
                  const float* __restrict__ beta,
                  const float* __restrict__ mean,
                  const float* __restrict__ var,
                  float* __restrict__ out) {
    extern __shared__ char dsm[];
    float  (*As)[128][32] = (float (*)[128][32])dsm;
    float  (*Bs)[128][32] = (float (*)[128][32])(dsm + PT_BS_OFF);
    __half (*bev)[BEVSTR] = (__half (*)[BEVSTR])dsm;   // overlay post-loop

    __shared__ int   pixs[4][128];
    __shared__ float wgts[4][128];
    __shared__ float scale_s[128];
    __shared__ float shift_s[128];

    const int t    = threadIdx.x;
    const int lane = t & 31;
    const int wid  = t >> 5;
    const int wm   = wid & 3;
    const int wn   = wid >> 2;
    const int qg   = lane >> 2;
    const int ql   = lane & 3;

    const int mBase = blockIdx.x * 128;

    const unsigned uA = smem_u32(&As[0][0][0]);
    const unsigned uB = smem_u32(&Bs[0][0][0]);

    auto load_stage = [&](int s, int buf) {
        #pragma unroll
        for (int i = 0; i < 2; i++) {
            int lin = t + i * 512;
            int m   = lin >> 3;
            int k4  = lin & 7;
            int kg  = s * 32 + k4 * 4;
            if (kg < CDIR) {
                const float* fb; int fs, off;
                if (kg < 16)       { fb = f16;  fs = 16; off = kg;       }
                else if (kg < 48)  { fb = f32;  fs = 32; off = kg - 16;  }
                else if (kg < 112) { fb = f64a; fs = 64; off = kg - 48;  }
                else               { fb = f64b; fs = 64; off = kg - 112; }
                unsigned wsw = (unsigned)((k4 * 4) ^ ((m & 3) << 3));
                unsigned dst = uA + ((unsigned)(buf * 128 + m) * 32 + wsw) * 4u;
                CP_ASYNC16(dst, fb + (size_t)(mBase + m) * fs + off);
            }
        }
        #pragma unroll
        for (int i = 0; i < 2; i++) {
            int lin = t + i * 512;
            int n   = lin >> 3;
            int k4  = lin & 7;
            int kg  = s * 32 + k4 * 4;
            if (kg < CDIR) {
                unsigned wsw = (unsigned)((k4 * 4) ^ ((n & 3) << 3));
                unsigned dst = uB + ((unsigned)(buf * 128 + n) * 32 + wsw) * 4u;
                CP_ASYNC16(dst, Wmat + (size_t)n * CIN + kg);
            }
        }
        CP_COMMIT();
    };

    load_stage(0, 0);
    load_stage(1, 1);

    if (t < 128) {
        float4 p = *(const float4*)(pc + (size_t)(mBase + t) * 4);
        int   bb = (int)p.x;
        float x  = (p.y - 0.0f) / 0.05f / 8.0f;
        float y  = (p.z - (-40.0f)) / 0.05f / 8.0f;
        int xf = (int)floorf(x);
        int yf = (int)floorf(y);
        int x0 = min(max(xf,     0), WGRID - 1);
        int x1 = min(max(xf + 1, 0), WGRID - 1);
        int y0 = min(max(yf,     0), HG - 1);
        int y1 = min(max(yf + 1, 0), HG - 1);
        float xf0 = (float)x0, xf1 = (float)x1;
        float yf0 = (float)y0, yf1 = (float)y1;
        int base = bb * HW;
        pixs[0][t] = base + y0 * WGRID + x0;
        pixs[1][t] = base + y1 * WGRID + x0;
        pixs[2][t] = base + y0 * WGRID + x1;
        pixs[3][t] = base + y1 * WGRID + x1;
        wgts[0][t] = (xf1 - x) * (yf1 - y);
        wgts[1][t] = (xf1 - x) * (y - yf0);
        wgts[2][t] = (x - xf0) * (yf1 - y);
        wgts[3][t] = (x - xf0) * (y - yf0);
    } else if (t < 256) {
        int n = t - 128;
        float s = gamma[n] * rsqrtf(var[n] + 1e-5f);
        scale_s[n] = s;
        shift_s[n] = beta[n] - mean[n] * s;
    }

    float acc[2][4][4];
    #pragma unroll
    for (int i = 0; i < 2; i++)
        #pragma unroll
        for (int j = 0; j < 4; j++)
            #pragma unroll
            for (int v = 0; v < 4; v++) acc[i][j][v] = 0.0f;

    for (int s = 0; s < NSTG_Q; s++) {
        int buf = s - (s / 3) * 3;
        if (s < NSTG_Q - 1) CP_WAIT(1); else CP_WAIT(0);
        __syncthreads();
        if (s + 2 < NSTG_Q) load_stage(s + 2, (s + 2) % 3);

        const int nk = (s == NSTG_Q - 1) ? 16 : 32;
        #pragma unroll
        for (int kk = 0; kk < 32; kk += 8) {
            if (kk < nk) {
                int kp = kk + 2 * ql;       // word pair (kp, kp+1) -> slots (ql, ql+4)
                unsigned a[2][4], bb[4][2];
                #pragma unroll
                for (int mt = 0; mt < 2; mt++) {
                    int r   = wm * 32 + mt * 16 + qg;
                    int wsw = kp ^ ((r & 3) << 3);      // (r+8)&3 == r&3
                    float2 v0 = *(const float2*)&As[buf][r][wsw];
                    float2 v1 = *(const float2*)&As[buf][r + 8][wsw];
                    a[mt][0] = __float_as_uint(v0.x);
                    a[mt][2] = __float_as_uint(v0.y);
                    a[mt][1] = __float_as_uint(v1.x);
                    a[mt][3] = __float_as_uint(v1.y);
                }
                #pragma unroll
                for (int nt = 0; nt < 4; nt++) {
                    int c   = wn * 32 + nt * 8 + qg;
                    int wsw = kp ^ ((c & 3) << 3);
                    float2 v = *(const float2*)&Bs[buf][c][wsw];
                    bb[nt][0] = __float_as_uint(v.x);
                    bb[nt][1] = __float_as_uint(v.y);
                }
                #pragma unroll
                for (int mt = 0; mt < 2; mt++)
                    #pragma unroll
                    for (int nt = 0; nt < 4; nt++)
                        mma_tf32(acc[mt][nt], a[mt], bb[nt]);
            }
        }
    }
    __syncthreads();   // GEMM buffers now free for bev overlay

    // --- warp-coalesced gather: 8 points per warp ---
    {
        int p0 = wid * 8;
        #pragma unroll
        for (int i = 0; i < 8; i++) {
            int m = p0 + i;
            float4 sum = make_float4(0.f, 0.f, 0.f, 0.f);
            #pragma unroll
            for (int nb = 0; nb < 4; nb++) {
                float w = wgts[nb][m];
                const __half* rp = g_G + (size_t)pixs[nb][m] * COUT + lane * 4;
                uint2 u = *(const uint2*)rp;
                float2 g0 = __half22float2(*(__half2*)&u.x);
                float2 g1 = __half22float2(*(__half2*)&u.y);
                sum.x += w * g0.x; sum.y += w * g0.y;
                sum.z += w * g1.x; sum.w += w * g1.y;
            }
            __half2 h0 = __floats2half2_rn(sum.x, sum.y);
            __half2 h1 = __floats2half2_rn(sum.z, sum.w);
            *(__half2*)&bev[m][lane * 4]     = h0;
            *(__half2*)&bev[m][lane * 4 + 2] = h1;
        }
    }
    __syncthreads();

    // add bev + BN + ReLU + store
    #pragma unroll
    for (int nt = 0; nt < 4; nt++) {
        int nl = wn * 32 + nt * 8 + 2 * ql;
        float s0 = scale_s[nl],     h0 = shift_s[nl];
        float s1 = scale_s[nl + 1], h1 = shift_s[nl + 1];
        #pragma unroll
        for (int mt = 0; mt < 2; mt++) {
            int ml = wm * 32 + mt * 16 + qg;
            float2 g0 = __half22float2(*(const __half2*)&bev[ml][nl]);
            float2 g1 = __half22float2(*(const __half2*)&bev[ml + 8][nl]);
            size_t o0 = (size_t)(mBase + ml) * COUT + nl;
            *(float2*)&out[o0] =
                make_float2(fmaxf((acc[mt][nt][0] + g0.x) * s0 + h0, 0.0f),
                            fmaxf((acc[mt][nt][1] + g0.y) * s1 + h1, 0.0f));
            *(float2*)&out[o0 + 8 * COUT] =
                make_float2(fmaxf((acc[mt][nt][2] + g1.x) * s0 + h0, 0.0f),
                            fmaxf((acc[mt][nt][3] + g1.y) * s1 + h1, 0.0f));
        }
    }
}

// ---------------------------------------------------------------------------
extern "C" void kernel_launch(void* const* d_in, const int* in_sizes, int n_in,
                              void* d_out, int out_size) {
    const float* point_coords = (const float*)d_in[0];
    const float* spatial      = (const float*)d_in[1];
    const float* feat16       = (const float*)d_in[2];
    const float* feat32       = (const float*)d_in[3];
    const float* feat64a      = (const float*)d_in[4];
    const float* feat64b      = (const float*)d_in[5];
    const float* Wmat         = (const float*)d_in[6];
    const float* gamma        = (const float*)d_in[7];
    const float* beta         = (const float*)d_in[8];
    const float* rmean        = (const float*)d_in[9];
    const float* rvar         = (const float*)d_in[10];
    float* out = (float*)d_out;

    cudaFuncSetAttribute(proj_kernel,
                         cudaFuncAttributeMaxDynamicSharedMemorySize, PROJ_SMEM);
    cudaFuncSetAttribute(point_kernel,
                         cudaFuncAttributeMaxDynamicSharedMemorySize, PT_SMEM);

    proj_kernel<<<NPIX / 128, 512, PROJ_SMEM>>>(spatial, Wmat);
    point_kernel<<<NPTS / 128, 512, PT_SMEM>>>(point_coords, feat16, feat32,
                                               feat64a, feat64b, Wmat,
                                               gamma, beta, rmean, rvar, out);
}

// round 16
// speedup vs baseline: 1.0737x; 1.0737x over previous
#include <cuda_runtime.h>
#include <cuda_fp16.h>
#include <math.h>
#include <stdint.h>

#define NPTS   262144
#define HG     200
#define WGRID  176
#define HW     35200
#define CBEV   256
#define CDIR   176
#define CIN    432
#define COUT   128
#define NPIX   140800

// Projected BEV features, fp16: G[pixel][128] = im[pixel][:] @ W[:,176:432]^T
__device__ __half g_G[(size_t)NPIX * COUT];   // 36 MB (L2-resident)

// ---------------------------------------------------------------------------
__device__ __forceinline__ unsigned smem_u32(const void* p) {
    unsigned a;
    asm("{ .reg .u64 t; cvta.to.shared.u64 t, %1; cvt.u32.u64 %0, t; }"
        : "=r"(a) : "l"(p));
    return a;
}
#define CP_ASYNC16(dst, src) \
    asm volatile("cp.async.cg.shared.global [%0], [%1], 16;\n" :: "r"(dst), "l"(src))
#define CP_COMMIT() asm volatile("cp.async.commit_group;\n")
#define CP_WAIT(n)  asm volatile("cp.async.wait_group %0;\n" :: "n"(n))

// Raw fp32 bits into tf32 MMA (RZ truncation in HW)
__device__ __forceinline__ void mma_tf32(float* c, const unsigned* a, const unsigned* b) {
    asm volatile(
        "mma.sync.aligned.m16n8k8.row.col.f32.tf32.tf32.f32 "
        "{%0,%1,%2,%3},{%4,%5,%6,%7},{%8,%9},{%0,%1,%2,%3};"
        : "+f"(c[0]), "+f"(c[1]), "+f"(c[2]), "+f"(c[3])
        : "r"(a[0]), "r"(a[1]), "r"(a[2]), "r"(a[3]), "r"(b[0]), "r"(b[1]));
}

// ---------------------------------------------------------------------------
// Kernel A (round-14 structure + PDL trigger): G = im @ W_bev^T, fp16 out.
// Tile 128x128, 512 threads, BK=32 (8 stages), 3-buffer pipeline.
// ---------------------------------------------------------------------------
#define ASTR_P 136
#define NSTG_P 8
#define PROJ_BS_OFF 52224
#define PROJ_SMEM   (52224 + 49152)

__global__ __launch_bounds__(512, 2)
void proj_kernel(const float* __restrict__ sp, const float* __restrict__ Wmat) {
    extern __shared__ char dsm[];
    float (*As)[32][ASTR_P] = (float (*)[32][ASTR_P])dsm;
    float (*Bs)[128][32]    = (float (*)[128][32])(dsm + PROJ_BS_OFF);

    // PDL: allow the dependent point_kernel grid to launch; it synchronizes
    // on this grid's completion before touching g_G.
    cudaTriggerProgrammaticLaunchCompletion();

    const int t    = threadIdx.x;
    const int lane = t & 31;
    const int wid  = t >> 5;
    const int wm   = wid & 3;
    const int wn   = wid >> 2;
    const int qg   = lane >> 2;
    const int ql   = lane & 3;

    const int pixBase = blockIdx.x * 128;
    const int b       = pixBase / HW;
    const int pixInB  = pixBase - b * HW;
    const float* Abase = sp + (size_t)b * CBEV * HW + pixInB;

    const unsigned uA = smem_u32(&As[0][0][0]);
    const unsigned uB = smem_u32(&Bs[0][0][0]);

    float acc[2][4][4];
    #pragma unroll
    for (int i = 0; i < 2; i++)
        #pragma unroll
        for (int j = 0; j < 4; j++)
            #pragma unroll
            for (int v = 0; v < 4; v++) acc[i][j][v] = 0.0f;

    auto load_stage = [&](int s, int buf) {
        int k0 = s * 32;
        #pragma unroll
        for (int i = 0; i < 2; i++) {
            int lin = t + i * 512;
            int k   = lin >> 5;
            int m4  = (lin & 31) << 2;
            unsigned dst = uA + ((unsigned)(buf * 32 + k) * ASTR_P + m4) * 4u;
            CP_ASYNC16(dst, Abase + (size_t)(k0 + k) * HW + m4);
        }
        #pragma unroll
        for (int i = 0; i < 2; i++) {
            int lin = t + i * 512;
            int n   = lin >> 3;
            int k4  = lin & 7;
            unsigned wsw = (unsigned)((k4 * 4) ^ ((n & 7) << 2));
            unsigned dst = uB + ((unsigned)(buf * 128 + n) * 32 + wsw) * 4u;
            CP_ASYNC16(dst, Wmat + (size_t)n * CIN + CDIR + k0 + k4 * 4);
        }
        CP_COMMIT();
    };

    load_stage(0, 0);
    load_stage(1, 1);

    for (int s = 0; s < NSTG_P; s++) {
        int buf = s - (s / 3) * 3;
        if (s < NSTG_P - 1) CP_WAIT(1); else CP_WAIT(0);
        __syncthreads();
        if (s + 2 < NSTG_P) load_stage(s + 2, (s + 2) % 3);

        #pragma unroll
        for (int kk = 0; kk < 32; kk += 8) {
            int kc = kk + ql;
            unsigned a[2][4], bb[4][2];
            #pragma unroll
            for (int mt = 0; mt < 2; mt++) {
                int r = wm * 32 + mt * 16 + qg;
                a[mt][0] = __float_as_uint(As[buf][kc][r]);
                a[mt][1] = __float_as_uint(As[buf][kc][r + 8]);
                a[mt][2] = __float_as_uint(As[buf][kc + 4][r]);
                a[mt][3] = __float_as_uint(As[buf][kc + 4][r + 8]);
            }
            #pragma unroll
            for (int nt = 0; nt < 4; nt++) {
                int c   = wn * 32 + nt * 8 + qg;
                int sw0 = kc ^ ((c & 7) << 2);
                int sw1 = (kc + 4) ^ ((c & 7) << 2);
                bb[nt][0] = __float_as_uint(Bs[buf][c][sw0]);
                bb[nt][1] = __float_as_uint(Bs[buf][c][sw1]);
            }
            #pragma unroll
            for (int mt = 0; mt < 2; mt++)
                #pragma unroll
                for (int nt = 0; nt < 4; nt++)
                    mma_tf32(acc[mt][nt], a[mt], bb[nt]);
        }
    }

    #pragma unroll
    for (int mt = 0; mt < 2; mt++) {
        int r0 = pixBase + wm * 32 + mt * 16 + qg;
        #pragma unroll
        for (int nt = 0; nt < 4; nt++) {
            int n = wn * 32 + nt * 8 + 2 * ql;
            *(__half2*)&g_G[(size_t)r0 * COUT + n] =
                __floats2half2_rn(acc[mt][nt][0], acc[mt][nt][1]);
            *(__half2*)&g_G[(size_t)(r0 + 8) * COUT + n] =
                __floats2half2_rn(acc[mt][nt][2], acc[mt][nt][3]);
        }
    }
}

// ---------------------------------------------------------------------------
// Kernel B (round-14 structure + PDL grid-sync): 128pts x 128out,
// 512 threads, BK=32 (6 stages incl. half-stage 5), 3-buffer pipeline,
// XOR-swizzled Bs. cudaGridDependencySynchronize() sits between the GEMM
// and the gather — the GEMM overlaps proj's tail under PDL.
// Dynamic smem: As[3][128][36] @0 (55296B), Bs[3][128][32] @55296 (49152B).
// ---------------------------------------------------------------------------
#define ASTR_Q 36
#define BEVSTR 136
#define NSTG_Q 6
#define PT_BS_OFF 55296
#define PT_SMEM   (55296 + 49152)

__global__ __launch_bounds__(512, 2)
void point_kernel(const float* __restrict__ pc,
                  const float* __restrict__ f16,
                  const float* __restrict__ f32,
                  const float* __restrict__ f64a,
                  const float* __restrict__ f64b,
                  const float* __restrict__ Wmat,
                  const float* __restrict__ gamma,
                  const float* __restrict__ beta,
                  const float* __restrict__ mean,
                  const float* __restrict__ var,
                  float* __restrict__ out) {
    extern __shared__ char dsm[];
    float  (*As)[128][ASTR_Q] = (float (*)[128][ASTR_Q])dsm;
    float  (*Bs)[128][32]     = (float (*)[128][32])(dsm + PT_BS_OFF);
    __half (*bev)[BEVSTR]     = (__half (*)[BEVSTR])dsm;   // overlay post-loop

    __shared__ int   pixs[4][128];
    __shared__ float wgts[4][128];
    __shared__ float scale_s[128];
    __shared__ float shift_s[128];

    const int t    = threadIdx.x;
    const int lane = t & 31;
    const int wid  = t >> 5;
    const int wm   = wid & 3;
    const int wn   = wid >> 2;
    const int qg   = lane >> 2;
    const int ql   = lane & 3;

    const int mBase = blockIdx.x * 128;

    const unsigned uA = smem_u32(&As[0][0][0]);
    const unsigned uB = smem_u32(&Bs[0][0][0]);

    auto load_stage = [&](int s, int buf) {
        #pragma unroll
        for (int i = 0; i < 2; i++) {
            int lin = t + i * 512;
            int m   = lin >> 3;
            int k4  = lin & 7;
            int kg  = s * 32 + k4 * 4;
            if (kg < CDIR) {
                const float* fb; int fs, off;
                if (kg < 16)       { fb = f16;  fs = 16; off = kg;       }
                else if (kg < 48)  { fb = f32;  fs = 32; off = kg - 16;  }
                else if (kg < 112) { fb = f64a; fs = 64; off = kg - 48;  }
                else               { fb = f64b; fs = 64; off = kg - 112; }
                unsigned dst = uA + ((unsigned)(buf * 128 + m) * ASTR_Q + k4 * 4) * 4u;
                CP_ASYNC16(dst, fb + (size_t)(mBase + m) * fs + off);
            }
        }
        #pragma unroll
        for (int i = 0; i < 2; i++) {
            int lin = t + i * 512;
            int n   = lin >> 3;
            int k4  = lin & 7;
            int kg  = s * 32 + k4 * 4;
            if (kg < CDIR) {
                unsigned wsw = (unsigned)((k4 * 4) ^ ((n & 7) << 2));
                unsigned dst = uB + ((unsigned)(buf * 128 + n) * 32 + wsw) * 4u;
                CP_ASYNC16(dst, Wmat + (size_t)n * CIN + kg);
            }
        }
        CP_COMMIT();
    };

    load_stage(0, 0);
    load_stage(1, 1);

    if (t < 128) {
        float4 p = *(const float4*)(pc + (size_t)(mBase + t) * 4);
        int   bb = (int)p.x;
        float x  = (p.y - 0.0f) / 0.05f / 8.0f;
        float y  = (p.z - (-40.0f)) / 0.05f / 8.0f;
        int xf = (int)floorf(x);
        int yf = (int)floorf(y);
        int x0 = min(max(xf,     0), WGRID - 1);
        int x1 = min(max(xf + 1, 0), WGRID - 1);
        int y0 = min(max(yf,     0), HG - 1);
        int y1 = min(max(yf + 1, 0), HG - 1);
        float xf0 = (float)x0, xf1 = (float)x1;
        float yf0 = (float)y0, yf1 = (float)y1;
        int base = bb * HW;
        pixs[0][t] = base + y0 * WGRID + x0;
        pixs[1][t] = base + y1 * WGRID + x0;
        pixs[2][t] = base + y0 * WGRID + x1;
        pixs[3][t] = base + y1 * WGRID + x1;
        wgts[0][t] = (xf1 - x) * (yf1 - y);
        wgts[1][t] = (xf1 - x) * (y - yf0);
        wgts[2][t] = (x - xf0) * (yf1 - y);
        wgts[3][t] = (x - xf0) * (y - yf0);
    } else if (t < 256) {
        int n = t - 128;
        float s = gamma[n] * rsqrtf(var[n] + 1e-5f);
        scale_s[n] = s;
        shift_s[n] = beta[n] - mean[n] * s;
    }

    float acc[2][4][4];
    #pragma unroll
    for (int i = 0; i < 2; i++)
        #pragma unroll
        for (int j = 0; j < 4; j++)
            #pragma unroll
            for (int v = 0; v < 4; v++) acc[i][j][v] = 0.0f;

    for (int s = 0; s < NSTG_Q; s++) {
        int buf = s - (s / 3) * 3;
        if (s < NSTG_Q - 1) CP_WAIT(1); else CP_WAIT(0);
        __syncthreads();
        if (s + 2 < NSTG_Q) load_stage(s + 2, (s + 2) % 3);

        const int nk = (s == NSTG_Q - 1) ? 16 : 32;
        #pragma unroll
        for (int kk = 0; kk < 32; kk += 8) {
            if (kk < nk) {
                int kc = kk + ql;
                unsigned a[2][4], bb[4][2];
                #pragma unroll
                for (int mt = 0; mt < 2; mt++) {
                    int r = wm * 32 + mt * 16 + qg;
                    a[mt][0] = __float_as_uint(As[buf][r][kc]);
                    a[mt][1] = __float_as_uint(As[buf][r + 8][kc]);
                    a[mt][2] = __float_as_uint(As[buf][r][kc + 4]);
                    a[mt][3] = __float_as_uint(As[buf][r + 8][kc + 4]);
                }
                #pragma unroll
                for (int nt = 0; nt < 4; nt++) {
                    int c   = wn * 32 + nt * 8 + qg;
                    int sw0 = kc ^ ((c & 7) << 2);
                    int sw1 = (kc + 4) ^ ((c & 7) << 2);
                    bb[nt][0] = __float_as_uint(Bs[buf][c][sw0]);
                    bb[nt][1] = __float_as_uint(Bs[buf][c][sw1]);
                }
                #pragma unroll
                for (int mt = 0; mt < 2; mt++)
                    #pragma unroll
                    for (int nt = 0; nt < 4; nt++)
                        mma_tf32(acc[mt][nt], a[mt], bb[nt]);
            }
        }
    }

    // PDL: wait for proj_kernel's grid (g_G writes) to be visible.
    cudaGridDependencySynchronize();
    __syncthreads();   // GEMM buffers now free for bev overlay

    // --- warp-coalesced gather: 8 points per warp ---
    {
        int p0 = wid * 8;
        #pragma unroll
        for (int i = 0; i < 8; i++) {
            int m = p0 + i;
            float4 sum = make_float4(0.f, 0.f, 0.f, 0.f);
            #pragma unroll
            for (int nb = 0; nb < 4; nb++) {
                float w = wgts[nb][m];
                const __half* rp = g_G + (size_t)pixs[nb][m] * COUT + lane * 4;
                uint2 u = *(const uint2*)rp;
                float2 g0 = __half22float2(*(__half2*)&u.x);
                float2 g1 = __half22float2(*(__half2*)&u.y);
                sum.x += w * g0.x; sum.y += w * g0.y;
                sum.z += w * g1.x; sum.w += w * g1.y;
            }
            __half2 h0 = __floats2half2_rn(sum.x, sum.y);
            __half2 h1 = __floats2half2_rn(sum.z, sum.w);
            *(__half2*)&bev[m][lane * 4]     = h0;
            *(__half2*)&bev[m][lane * 4 + 2] = h1;
        }
    }
    __syncthreads();

    // add bev + BN + ReLU + store
    #pragma unroll
    for (int nt = 0; nt < 4; nt++) {
        int nl = wn * 32 + nt * 8 + 2 * ql;
        float s0 = scale_s[nl],     h0 = shift_s[nl];
        float s1 = scale_s[nl + 1], h1 = shift_s[nl + 1];
        #pragma unroll
        for (int mt = 0; mt < 2; mt++) {
            int ml = wm * 32 + mt * 16 + qg;
            float2 g0 = __half22float2(*(const __half2*)&bev[ml][nl]);
            float2 g1 = __half22float2(*(const __half2*)&bev[ml + 8][nl]);
            size_t o0 = (size_t)(mBase + ml) * COUT + nl;
            *(float2*)&out[o0] =
                make_float2(fmaxf((acc[mt][nt][0] + g0.x) * s0 + h0, 0.0f),
                            fmaxf((acc[mt][nt][1] + g0.y) * s1 + h1, 0.0f));
            *(float2*)&out[o0 + 8 * COUT] =
                make_float2(fmaxf((acc[mt][nt][2] + g1.x) * s0 + h0, 0.0f),
                            fmaxf((acc[mt][nt][3] + g1.y) * s1 + h1, 0.0f));
        }
    }
}

// ---------------------------------------------------------------------------
extern "C" void kernel_launch(void* const* d_in, const int* in_sizes, int n_in,
                              void* d_out, int out_size) {
    const float* point_coords = (const float*)d_in[0];
    const float* spatial      = (const float*)d_in[1];
    const float* feat16       = (const float*)d_in[2];
    const float* feat32       = (const float*)d_in[3];
    const float* feat64a      = (const float*)d_in[4];
    const float* feat64b      = (const float*)d_in[5];
    const float* Wmat         = (const float*)d_in[6];
    const float* gamma        = (const float*)d_in[7];
    const float* beta         = (const float*)d_in[8];
    const float* rmean        = (const float*)d_in[9];
    const float* rvar         = (const float*)d_in[10];
    float* out = (float*)d_out;

    cudaFuncSetAttribute(proj_kernel,
                         cudaFuncAttributeMaxDynamicSharedMemorySize, PROJ_SMEM);
    cudaFuncSetAttribute(point_kernel,
                         cudaFuncAttributeMaxDynamicSharedMemorySize, PT_SMEM);

    proj_kernel<<<NPIX / 128, 512, PROJ_SMEM>>>(spatial, Wmat);

    // Programmatic dependent launch: point_kernel launches while proj's
    // tail executes; correctness enforced by cudaGridDependencySynchronize()
    // inside point_kernel before the g_G gather.
    cudaLaunchConfig_t cfg = {};
    cfg.gridDim  = dim3(NPTS / 128, 1, 1);
    cfg.blockDim = dim3(512, 1, 1);
    cfg.dynamicSmemBytes = PT_SMEM;
    cudaLaunchAttribute attrs[1];
    attrs[0].id = cudaLaunchAttributeProgrammaticStreamSerialization;
    attrs[0].val.programmaticStreamSerializationAllowed = 1;
    cfg.attrs = attrs;
    cfg.numAttrs = 1;
    cudaLaunchKernelEx(&cfg, point_kernel,
                       point_coords, feat16, feat32, feat64a, feat64b,
                       Wmat, gamma, beta, rmean, rvar, out);
}